// round 6
// baseline (speedup 1.0000x reference)
#include <cuda_runtime.h>
#include <cstdint>

#define BB  4
#define NN  16384
#define SS  4096
#define KK  32
#define CINF 16
#define C0  19
#define C1  32
#define C2  32
#define C3  64
#define EPSF 1e-5f

#define TILE 2048
#define WQ   8

// ---------------- scratch (no allocs allowed) ----------------
__device__ int   g_knn[BB * SS * KK];
__device__ float g_a1[C1], g_b1[C1];   // BN post-affine A, B
__device__ float g_a2[C2], g_b2[C2];
__device__ float g_a3[C3], g_b3[C3];

// ---------------- prep: fold BN as post-affine (weights stay raw fp32) ----------
__global__ void prep_kernel(
    const float* __restrict__ b0,
    const float* __restrict__ g0, const float* __restrict__ bt0,
    const float* __restrict__ rm0, const float* __restrict__ rv0,
    const float* __restrict__ b1,
    const float* __restrict__ g1, const float* __restrict__ bt1,
    const float* __restrict__ rm1, const float* __restrict__ rv1,
    const float* __restrict__ b2,
    const float* __restrict__ g2, const float* __restrict__ bt2,
    const float* __restrict__ rm2, const float* __restrict__ rv2)
{
    int t = threadIdx.x;
    if (t < C1) {
        float A = g0[t] * rsqrtf(rv0[t] + EPSF);
        g_a1[t] = A;
        g_b1[t] = (b0[t] - rm0[t]) * A + bt0[t];
    }
    if (t < C2) {
        float A = g1[t] * rsqrtf(rv1[t] + EPSF);
        g_a2[t] = A;
        g_b2[t] = (b1[t] - rm1[t]) * A + bt1[t];
    }
    if (t < C3) {
        float A = g2[t] * rsqrtf(rv2[t] + EPSF);
        g_a3[t] = A;
        g_b3[t] = (b2[t] - rm2[t]) * A + bt2[t];
    }
}

// ---------------- KNN: warp handles WQ=8 queries, distributed top-32 -------------
// Bitwise model of the reference lowering (unchanged from passing R5):
//   qq, pp : (x*x + y*y) + z*z, mul+add, NO fma
//   dot    : fma(qz,pz, fma(qy,py, rn(qx*px)))
//   d      : (qq - 2*dot) + pp, NO fma
// New: cached lane-31 threshold (kd,ki), refreshed only after inserts;
//      filter d <= kd (tie/worse-index candidates self-drop at pos==32);
//      meta outputs (new_xyz, sample_idx) folded into init.
__global__ void __launch_bounds__(256)
knn_kernel(const float* __restrict__ xyz, const int* __restrict__ sidx,
           float* __restrict__ out)
{
    __shared__ float4 tile[TILE];   // (x, y, z, ||p||^2 no-fma)
    const unsigned FULL = 0xffffffffu;
    int warp = threadIdx.x >> 5;
    int lane = threadIdx.x & 31;

    int b = blockIdx.x >> 6;                       // 64 blocks per batch
    int sbase = (blockIdx.x & 63) * 64 + warp * WQ;

    float qx[WQ], qy[WQ], qz[WQ], qq[WQ], ld[WQ], kd[WQ];
    int li[WQ], ki[WQ];
#pragma unroll
    for (int i = 0; i < WQ; i++) {
        int s = b * SS + sbase + i;
        int sid = sidx[s];
        const float* p = xyz + ((size_t)b * NN + sid) * 3;
        float x = p[0], y = p[1], z = p[2];
        qq[i] = __fadd_rn(__fadd_rn(__fmul_rn(x, x), __fmul_rn(y, y)),
                          __fmul_rn(z, z));
        qx[i] = x; qy[i] = y; qz[i] = z;
        ld[i] = __int_as_float(0x7f800000);        // +inf
        li[i] = 0x7fffffff;
        kd[i] = ld[i];
        ki[i] = li[i];
        if (lane == i) {                            // fold meta outputs
            out[s * 3 + 0] = x;
            out[s * 3 + 1] = y;
            out[s * 3 + 2] = z;
            out[(size_t)BB * SS * 3 + (size_t)BB * SS * C3 + s] = (float)sid;
        }
    }

    const float* base = xyz + (size_t)b * NN * 3;
    for (int t = 0; t < NN; t += TILE) {
        __syncthreads();
        for (int j = threadIdx.x; j < TILE; j += 256) {
            const float* p = base + (size_t)(t + j) * 3;
            float x = p[0], y = p[1], z = p[2];
            float pp = __fadd_rn(__fadd_rn(__fmul_rn(x, x), __fmul_rn(y, y)),
                                 __fmul_rn(z, z));
            tile[j] = make_float4(x, y, z, pp);
        }
        __syncthreads();

        for (int j = 0; j < TILE; j += 32) {
            float4 p = tile[j + lane];
            int gi = t + j + lane;
#pragma unroll
            for (int i = 0; i < WQ; i++) {
                float dot = __fmaf_rn(qz[i], p.z,
                            __fmaf_rn(qy[i], p.y, __fmul_rn(qx[i], p.x)));
                float d = __fadd_rn(__fsub_rn(qq[i], __fmul_rn(2.0f, dot)), p.w);
                unsigned m = __ballot_sync(FULL, d <= kd[i]);
                if (m) {
                    do {
                        int src = __ffs(m) - 1;
                        m &= m - 1;
                        float cd = __shfl_sync(FULL, d, src);
                        int   ci = __shfl_sync(FULL, gi, src);
                        // position = #elements strictly better than candidate
                        bool eb = (ld[i] < cd) || (ld[i] == cd && li[i] < ci);
                        int pos = __popc(__ballot_sync(FULL, eb));
                        float sd = __shfl_up_sync(FULL, ld[i], 1);
                        int   si = __shfl_up_sync(FULL, li[i], 1);
                        if (lane == pos)      { ld[i] = cd; li[i] = ci; }
                        else if (lane > pos)  { ld[i] = sd; li[i] = si; }
                    } while (m);
                    kd[i] = __shfl_sync(FULL, ld[i], 31);
                    ki[i] = __shfl_sync(FULL, li[i], 31);
                }
            }
        }
    }
#pragma unroll
    for (int i = 0; i < WQ; i++)
        g_knn[((size_t)(b * SS + sbase + i)) * KK + lane] = li[i];
}

// ---------------- distributed warp max-reduce stage ----------------
template <int M, int SH>
__device__ __forceinline__ void redstage(float* o, int l)
{
    int bit = (l >> SH) & 1;
#pragma unroll
    for (int i = 0; i < M; i++) {
        float snd = bit ? o[i] : o[M + i];
        float rcv = __shfl_xor_sync(0xffffffffu, snd, 1 << SH);
        float mine = bit ? o[M + i] : o[i];
        o[i] = fmaxf(mine, rcv);
    }
}

// ---------------- MLP + maxpool: warp per query, lane per neighbor ----------------
__global__ void __launch_bounds__(256)
mlp_kernel(const float* __restrict__ xyz, const float* __restrict__ feat,
           const int* __restrict__ sidx,
           const float* __restrict__ w1g, const float* __restrict__ w2g,
           const float* __restrict__ w3g,
           float* __restrict__ out)
{
    __shared__ float sW1[C0 * C1], sW2[C1 * C2], sW3[C2 * C3];
    __shared__ float sA1[C1], sB1[C1], sA2[C2], sB2[C2], sA3[C3], sB3[C3];
    for (int i = threadIdx.x; i < C0 * C1; i += 256) sW1[i] = w1g[i];
    for (int i = threadIdx.x; i < C1 * C2; i += 256) sW2[i] = w2g[i];
    for (int i = threadIdx.x; i < C2 * C3; i += 256) sW3[i] = w3g[i];
    if (threadIdx.x < C1) { sA1[threadIdx.x] = g_a1[threadIdx.x]; sB1[threadIdx.x] = g_b1[threadIdx.x]; }
    if (threadIdx.x < C2) { sA2[threadIdx.x] = g_a2[threadIdx.x]; sB2[threadIdx.x] = g_b2[threadIdx.x]; }
    if (threadIdx.x < C3) { sA3[threadIdx.x] = g_a3[threadIdx.x]; sB3[threadIdx.x] = g_b3[threadIdx.x]; }
    __syncthreads();

    int warp = threadIdx.x >> 5;
    int lane = threadIdx.x & 31;
    int qid = blockIdx.x * 8 + warp;               // 0 .. B*S-1
    int b = qid >> 12;                              // / SS

    int sid = sidx[qid];
    const float* qp = xyz + ((size_t)b * NN + sid) * 3;
    float qx = qp[0], qy = qp[1], qz = qp[2];

    int nb = g_knn[(size_t)qid * KK + lane];
    const float* pp = xyz + ((size_t)b * NN + nb) * 3;

    float x[C0];
    x[0] = pp[0] - qx;
    x[1] = pp[1] - qy;
    x[2] = pp[2] - qz;
    const float4* f4 = (const float4*)(feat + ((size_t)b * NN + nb) * CINF);
#pragma unroll
    for (int v = 0; v < 4; v++) {
        float4 fv = f4[v];
        x[3 + 4 * v] = fv.x; x[4 + 4 * v] = fv.y;
        x[5 + 4 * v] = fv.z; x[6 + 4 * v] = fv.w;
    }

    // layer 1: 19 -> 32  (exact fp32, BN post-affine, ReLU)
    float y[C1];
#pragma unroll
    for (int d = 0; d < C1; d++) y[d] = 0.0f;
    {
        const float4* Wv = (const float4*)sW1;
#pragma unroll
        for (int c = 0; c < C0; c++) {
            float xc = x[c];
#pragma unroll
            for (int d4 = 0; d4 < C1 / 4; d4++) {
                float4 wv = Wv[c * (C1 / 4) + d4];
                y[4 * d4 + 0] = fmaf(xc, wv.x, y[4 * d4 + 0]);
                y[4 * d4 + 1] = fmaf(xc, wv.y, y[4 * d4 + 1]);
                y[4 * d4 + 2] = fmaf(xc, wv.z, y[4 * d4 + 2]);
                y[4 * d4 + 3] = fmaf(xc, wv.w, y[4 * d4 + 3]);
            }
        }
    }
#pragma unroll
    for (int d = 0; d < C1; d++)
        y[d] = fmaxf(fmaf(y[d], sA1[d], sB1[d]), 0.0f);

    // layer 2: 32 -> 32
    float z[C2];
#pragma unroll
    for (int d = 0; d < C2; d++) z[d] = 0.0f;
    {
        const float4* Wv = (const float4*)sW2;
#pragma unroll
        for (int c = 0; c < C1; c++) {
            float xc = y[c];
#pragma unroll
            for (int d4 = 0; d4 < C2 / 4; d4++) {
                float4 wv = Wv[c * (C2 / 4) + d4];
                z[4 * d4 + 0] = fmaf(xc, wv.x, z[4 * d4 + 0]);
                z[4 * d4 + 1] = fmaf(xc, wv.y, z[4 * d4 + 1]);
                z[4 * d4 + 2] = fmaf(xc, wv.z, z[4 * d4 + 2]);
                z[4 * d4 + 3] = fmaf(xc, wv.w, z[4 * d4 + 3]);
            }
        }
    }
#pragma unroll
    for (int d = 0; d < C2; d++)
        z[d] = fmaxf(fmaf(z[d], sA2[d], sB2[d]), 0.0f);

    // layer 3: 32 -> 64
    float o[C3];
#pragma unroll
    for (int d = 0; d < C3; d++) o[d] = 0.0f;
    {
        const float4* Wv = (const float4*)sW3;
#pragma unroll
        for (int c = 0; c < C2; c++) {
            float xc = z[c];
#pragma unroll
            for (int d4 = 0; d4 < C3 / 4; d4++) {
                float4 wv = Wv[c * (C3 / 4) + d4];
                o[4 * d4 + 0] = fmaf(xc, wv.x, o[4 * d4 + 0]);
                o[4 * d4 + 1] = fmaf(xc, wv.y, o[4 * d4 + 1]);
                o[4 * d4 + 2] = fmaf(xc, wv.z, o[4 * d4 + 2]);
                o[4 * d4 + 3] = fmaf(xc, wv.w, o[4 * d4 + 3]);
            }
        }
    }
#pragma unroll
    for (int d = 0; d < C3; d++)
        o[d] = fmaxf(fmaf(o[d], sA3[d], sB3[d]), 0.0f);

    // max over K=32 neighbors: channel-splitting butterfly.
    redstage<32, 0>(o, lane);
    redstage<16, 1>(o, lane);
    redstage<8,  2>(o, lane);
    redstage<4,  3>(o, lane);
    redstage<2,  4>(o, lane);

    int chb = (((lane >> 0) & 1) << 5) | (((lane >> 1) & 1) << 4) |
              (((lane >> 2) & 1) << 3) | (((lane >> 3) & 1) << 2) |
              (((lane >> 4) & 1) << 1);

    float* dst = out + (size_t)BB * SS * 3 + (size_t)qid * C3 + chb;
    *(float2*)dst = make_float2(o[0], o[1]);
}

// ---------------- launch ----------------
extern "C" void kernel_launch(void* const* d_in, const int* in_sizes, int n_in,
                              void* d_out, int out_size)
{
    const float* xyz     = (const float*)d_in[0];
    const float* feature = (const float*)d_in[1];
    const int*   sidx    = (const int*)d_in[2];

    const float* w0  = (const float*)d_in[3];
    const float* b0  = (const float*)d_in[4];
    const float* g0  = (const float*)d_in[5];
    const float* bt0 = (const float*)d_in[6];
    const float* rm0 = (const float*)d_in[7];
    const float* rv0 = (const float*)d_in[8];
    const float* w1  = (const float*)d_in[9];
    const float* b1  = (const float*)d_in[10];
    const float* g1  = (const float*)d_in[11];
    const float* bt1 = (const float*)d_in[12];
    const float* rm1 = (const float*)d_in[13];
    const float* rv1 = (const float*)d_in[14];
    const float* w2  = (const float*)d_in[15];
    const float* b2  = (const float*)d_in[16];
    const float* g2  = (const float*)d_in[17];
    const float* bt2 = (const float*)d_in[18];
    const float* rm2 = (const float*)d_in[19];
    const float* rv2 = (const float*)d_in[20];

    float* out = (float*)d_out;

    prep_kernel<<<1, 256>>>(b0, g0, bt0, rm0, rv0,
                            b1, g1, bt1, rm1, rv1,
                            b2, g2, bt2, rm2, rv2);
    knn_kernel<<<(BB * SS) / (8 * WQ), 256>>>(xyz, sidx, out);
    mlp_kernel<<<(BB * SS) / 8, 256>>>(xyz, feature, sidx, w0, w1, w2, out);
}

// round 7
// speedup vs baseline: 1.2579x; 1.2579x over previous
#include <cuda_runtime.h>
#include <cstdint>

#define BB  4
#define NN  16384
#define SS  4096
#define KK  32
#define CINF 16
#define C0  19
#define C1  32
#define C2  32
#define C3  64
#define EPSF 1e-5f

#define TILE 2048
#define WQ   4

// ---------------- scratch (no allocs allowed) ----------------
__device__ int   g_knn[BB * SS * KK];
__device__ float g_a1[C1], g_b1[C1];   // BN post-affine A, B
__device__ float g_a2[C2], g_b2[C2];
__device__ float g_a3[C3], g_b3[C3];

// ---------------- prep: fold BN as post-affine (weights stay raw fp32) ----------
__global__ void prep_kernel(
    const float* __restrict__ b0,
    const float* __restrict__ g0, const float* __restrict__ bt0,
    const float* __restrict__ rm0, const float* __restrict__ rv0,
    const float* __restrict__ b1,
    const float* __restrict__ g1, const float* __restrict__ bt1,
    const float* __restrict__ rm1, const float* __restrict__ rv1,
    const float* __restrict__ b2,
    const float* __restrict__ g2, const float* __restrict__ bt2,
    const float* __restrict__ rm2, const float* __restrict__ rv2)
{
    int t = threadIdx.x;
    if (t < C1) {
        float A = g0[t] * rsqrtf(rv0[t] + EPSF);
        g_a1[t] = A;
        g_b1[t] = (b0[t] - rm0[t]) * A + bt0[t];
    }
    if (t < C2) {
        float A = g1[t] * rsqrtf(rv1[t] + EPSF);
        g_a2[t] = A;
        g_b2[t] = (b1[t] - rm1[t]) * A + bt1[t];
    }
    if (t < C3) {
        float A = g2[t] * rsqrtf(rv2[t] + EPSF);
        g_a3[t] = A;
        g_b3[t] = (b2[t] - rm2[t]) * A + bt2[t];
    }
}

// ---------------- KNN: warp handles WQ=4 queries, distributed top-32 -------------
// Bitwise model of the reference lowering (same distances as passing R5):
//   qq, pp : (x*x + y*y) + z*z, mul+add, NO fma
//   dot2   : fma(2qz,pz, fma(2qy,py, rn(2qx*px)))  ==  2*dot bitwise
//            (power-of-2 scaling is exact and commutes with rounding)
//   d      : (qq - dot2) + pp, NO fma
// Threshold (kd) cached from lane 31, refreshed only after inserts; filter
// d <= kd (tie/worse-index candidates self-drop at pos==32). Meta outputs
// (new_xyz, sample_idx) folded into init.
__global__ void __launch_bounds__(256)
knn_kernel(const float* __restrict__ xyz, const int* __restrict__ sidx,
           float* __restrict__ out)
{
    __shared__ float4 tile[TILE];   // (x, y, z, ||p||^2 no-fma)
    const unsigned FULL = 0xffffffffu;
    int warp = threadIdx.x >> 5;
    int lane = threadIdx.x & 31;

    int b = blockIdx.x >> 7;                       // 128 blocks per batch
    int sbase = (blockIdx.x & 127) * 32 + warp * WQ;

    float qx2[WQ], qy2[WQ], qz2[WQ], qq[WQ], ld[WQ], kd[WQ];
    int li[WQ];
#pragma unroll
    for (int i = 0; i < WQ; i++) {
        int s = b * SS + sbase + i;
        int sid = sidx[s];
        const float* p = xyz + ((size_t)b * NN + sid) * 3;
        float x = p[0], y = p[1], z = p[2];
        qq[i] = __fadd_rn(__fadd_rn(__fmul_rn(x, x), __fmul_rn(y, y)),
                          __fmul_rn(z, z));
        qx2[i] = 2.0f * x; qy2[i] = 2.0f * y; qz2[i] = 2.0f * z;
        ld[i] = __int_as_float(0x7f800000);        // +inf
        li[i] = 0x7fffffff;
        kd[i] = ld[i];
        if (lane == i) {                            // fold meta outputs
            out[s * 3 + 0] = x;
            out[s * 3 + 1] = y;
            out[s * 3 + 2] = z;
            out[(size_t)BB * SS * 3 + (size_t)BB * SS * C3 + s] = (float)sid;
        }
    }

    const float* base = xyz + (size_t)b * NN * 3;
    for (int t = 0; t < NN; t += TILE) {
        __syncthreads();
        for (int j = threadIdx.x; j < TILE; j += 256) {
            const float* p = base + (size_t)(t + j) * 3;
            float x = p[0], y = p[1], z = p[2];
            float pp = __fadd_rn(__fadd_rn(__fmul_rn(x, x), __fmul_rn(y, y)),
                                 __fmul_rn(z, z));
            tile[j] = make_float4(x, y, z, pp);
        }
        __syncthreads();

        for (int j = 0; j < TILE; j += 32) {
            float4 p = tile[j + lane];
            int gi = t + j + lane;
#pragma unroll
            for (int i = 0; i < WQ; i++) {
                float dot2 = __fmaf_rn(qz2[i], p.z,
                             __fmaf_rn(qy2[i], p.y, __fmul_rn(qx2[i], p.x)));
                float d = __fadd_rn(__fsub_rn(qq[i], dot2), p.w);
                unsigned m = __ballot_sync(FULL, d <= kd[i]);
                if (m) {
                    do {
                        int src = __ffs(m) - 1;
                        m &= m - 1;
                        float cd = __shfl_sync(FULL, d, src);
                        int   ci = __shfl_sync(FULL, gi, src);
                        // position = #elements strictly better than candidate
                        bool eb = (ld[i] < cd) || (ld[i] == cd && li[i] < ci);
                        int pos = __popc(__ballot_sync(FULL, eb));
                        float sd = __shfl_up_sync(FULL, ld[i], 1);
                        int   si = __shfl_up_sync(FULL, li[i], 1);
                        if (lane == pos)      { ld[i] = cd; li[i] = ci; }
                        else if (lane > pos)  { ld[i] = sd; li[i] = si; }
                    } while (m);
                    kd[i] = __shfl_sync(FULL, ld[i], 31);
                }
            }
        }
    }
#pragma unroll
    for (int i = 0; i < WQ; i++)
        g_knn[((size_t)(b * SS + sbase + i)) * KK + lane] = li[i];
}

// ---------------- distributed warp max-reduce stage ----------------
template <int M, int SH>
__device__ __forceinline__ void redstage(float* o, int l)
{
    int bit = (l >> SH) & 1;
#pragma unroll
    for (int i = 0; i < M; i++) {
        float snd = bit ? o[i] : o[M + i];
        float rcv = __shfl_xor_sync(0xffffffffu, snd, 1 << SH);
        float mine = bit ? o[M + i] : o[i];
        o[i] = fmaxf(mine, rcv);
    }
}

// ---------------- MLP + maxpool: warp per query, lane per neighbor ----------------
__global__ void __launch_bounds__(256)
mlp_kernel(const float* __restrict__ xyz, const float* __restrict__ feat,
           const int* __restrict__ sidx,
           const float* __restrict__ w1g, const float* __restrict__ w2g,
           const float* __restrict__ w3g,
           float* __restrict__ out)
{
    __shared__ float sW1[C0 * C1], sW2[C1 * C2], sW3[C2 * C3];
    __shared__ float sA1[C1], sB1[C1], sA2[C2], sB2[C2], sA3[C3], sB3[C3];
    for (int i = threadIdx.x; i < C0 * C1; i += 256) sW1[i] = w1g[i];
    for (int i = threadIdx.x; i < C1 * C2; i += 256) sW2[i] = w2g[i];
    for (int i = threadIdx.x; i < C2 * C3; i += 256) sW3[i] = w3g[i];
    if (threadIdx.x < C1) { sA1[threadIdx.x] = g_a1[threadIdx.x]; sB1[threadIdx.x] = g_b1[threadIdx.x]; }
    if (threadIdx.x < C2) { sA2[threadIdx.x] = g_a2[threadIdx.x]; sB2[threadIdx.x] = g_b2[threadIdx.x]; }
    if (threadIdx.x < C3) { sA3[threadIdx.x] = g_a3[threadIdx.x]; sB3[threadIdx.x] = g_b3[threadIdx.x]; }
    __syncthreads();

    int warp = threadIdx.x >> 5;
    int lane = threadIdx.x & 31;
    int qid = blockIdx.x * 8 + warp;               // 0 .. B*S-1
    int b = qid >> 12;                              // / SS

    int sid = sidx[qid];
    const float* qp = xyz + ((size_t)b * NN + sid) * 3;
    float qx = qp[0], qy = qp[1], qz = qp[2];

    int nb = g_knn[(size_t)qid * KK + lane];
    const float* pp = xyz + ((size_t)b * NN + nb) * 3;

    float x[C0];
    x[0] = pp[0] - qx;
    x[1] = pp[1] - qy;
    x[2] = pp[2] - qz;
    const float4* f4 = (const float4*)(feat + ((size_t)b * NN + nb) * CINF);
#pragma unroll
    for (int v = 0; v < 4; v++) {
        float4 fv = f4[v];
        x[3 + 4 * v] = fv.x; x[4 + 4 * v] = fv.y;
        x[5 + 4 * v] = fv.z; x[6 + 4 * v] = fv.w;
    }

    // layer 1: 19 -> 32  (exact fp32, BN post-affine, ReLU)
    float y[C1];
#pragma unroll
    for (int d = 0; d < C1; d++) y[d] = 0.0f;
    {
        const float4* Wv = (const float4*)sW1;
#pragma unroll
        for (int c = 0; c < C0; c++) {
            float xc = x[c];
#pragma unroll
            for (int d4 = 0; d4 < C1 / 4; d4++) {
                float4 wv = Wv[c * (C1 / 4) + d4];
                y[4 * d4 + 0] = fmaf(xc, wv.x, y[4 * d4 + 0]);
                y[4 * d4 + 1] = fmaf(xc, wv.y, y[4 * d4 + 1]);
                y[4 * d4 + 2] = fmaf(xc, wv.z, y[4 * d4 + 2]);
                y[4 * d4 + 3] = fmaf(xc, wv.w, y[4 * d4 + 3]);
            }
        }
    }
#pragma unroll
    for (int d = 0; d < C1; d++)
        y[d] = fmaxf(fmaf(y[d], sA1[d], sB1[d]), 0.0f);

    // layer 2: 32 -> 32
    float z[C2];
#pragma unroll
    for (int d = 0; d < C2; d++) z[d] = 0.0f;
    {
        const float4* Wv = (const float4*)sW2;
#pragma unroll
        for (int c = 0; c < C1; c++) {
            float xc = y[c];
#pragma unroll
            for (int d4 = 0; d4 < C2 / 4; d4++) {
                float4 wv = Wv[c * (C2 / 4) + d4];
                z[4 * d4 + 0] = fmaf(xc, wv.x, z[4 * d4 + 0]);
                z[4 * d4 + 1] = fmaf(xc, wv.y, z[4 * d4 + 1]);
                z[4 * d4 + 2] = fmaf(xc, wv.z, z[4 * d4 + 2]);
                z[4 * d4 + 3] = fmaf(xc, wv.w, z[4 * d4 + 3]);
            }
        }
    }
#pragma unroll
    for (int d = 0; d < C2; d++)
        z[d] = fmaxf(fmaf(z[d], sA2[d], sB2[d]), 0.0f);

    // layer 3: 32 -> 64
    float o[C3];
#pragma unroll
    for (int d = 0; d < C3; d++) o[d] = 0.0f;
    {
        const float4* Wv = (const float4*)sW3;
#pragma unroll
        for (int c = 0; c < C2; c++) {
            float xc = z[c];
#pragma unroll
            for (int d4 = 0; d4 < C3 / 4; d4++) {
                float4 wv = Wv[c * (C3 / 4) + d4];
                o[4 * d4 + 0] = fmaf(xc, wv.x, o[4 * d4 + 0]);
                o[4 * d4 + 1] = fmaf(xc, wv.y, o[4 * d4 + 1]);
                o[4 * d4 + 2] = fmaf(xc, wv.z, o[4 * d4 + 2]);
                o[4 * d4 + 3] = fmaf(xc, wv.w, o[4 * d4 + 3]);
            }
        }
    }
#pragma unroll
    for (int d = 0; d < C3; d++)
        o[d] = fmaxf(fmaf(o[d], sA3[d], sB3[d]), 0.0f);

    // max over K=32 neighbors: channel-splitting butterfly.
    redstage<32, 0>(o, lane);
    redstage<16, 1>(o, lane);
    redstage<8,  2>(o, lane);
    redstage<4,  3>(o, lane);
    redstage<2,  4>(o, lane);

    int chb = (((lane >> 0) & 1) << 5) | (((lane >> 1) & 1) << 4) |
              (((lane >> 2) & 1) << 3) | (((lane >> 3) & 1) << 2) |
              (((lane >> 4) & 1) << 1);

    float* dst = out + (size_t)BB * SS * 3 + (size_t)qid * C3 + chb;
    *(float2*)dst = make_float2(o[0], o[1]);
}

// ---------------- launch ----------------
extern "C" void kernel_launch(void* const* d_in, const int* in_sizes, int n_in,
                              void* d_out, int out_size)
{
    const float* xyz     = (const float*)d_in[0];
    const float* feature = (const float*)d_in[1];
    const int*   sidx    = (const int*)d_in[2];

    const float* w0  = (const float*)d_in[3];
    const float* b0  = (const float*)d_in[4];
    const float* g0  = (const float*)d_in[5];
    const float* bt0 = (const float*)d_in[6];
    const float* rm0 = (const float*)d_in[7];
    const float* rv0 = (const float*)d_in[8];
    const float* w1  = (const float*)d_in[9];
    const float* b1  = (const float*)d_in[10];
    const float* g1  = (const float*)d_in[11];
    const float* bt1 = (const float*)d_in[12];
    const float* rm1 = (const float*)d_in[13];
    const float* rv1 = (const float*)d_in[14];
    const float* w2  = (const float*)d_in[15];
    const float* b2  = (const float*)d_in[16];
    const float* g2  = (const float*)d_in[17];
    const float* bt2 = (const float*)d_in[18];
    const float* rm2 = (const float*)d_in[19];
    const float* rv2 = (const float*)d_in[20];

    float* out = (float*)d_out;

    prep_kernel<<<1, 256>>>(b0, g0, bt0, rm0, rv0,
                            b1, g1, bt1, rm1, rv1,
                            b2, g2, bt2, rm2, rv2);
    knn_kernel<<<(BB * SS) / (8 * WQ), 256>>>(xyz, sidx, out);
    mlp_kernel<<<(BB * SS) / 8, 256>>>(xyz, feature, sidx, w0, w1, w2, out);
}